// round 7
// baseline (speedup 1.0000x reference)
#include <cuda_runtime.h>
#include <cuda_fp16.h>

#define HID   2048
#define FH    8192   // 4*H
#define TLEN  8192
#define NCTA  128
#define TPB   512
#define JPC   16     // h-lanes per CTA (2048/128)

// SMEM: 32 weight rows (2 per warp) * 2048 halves = 131072 B
//       + h stage 2048 halves = 4096 B + bias 64 f + wih 192 f = 1024 B
#define SMEM_W_BYTES (32 * HID * 2)
#define SMEM_BYTES   (SMEM_W_BYTES + HID * 2 + (64 + 192) * 4)

// ---- device scratch (static only; no cudaMalloc allowed) ----
__device__ __align__(16) __half g_Whh[(size_t)FH * HID];  // 32 MB fp16 weights
__device__ __align__(16) __half g_hh[2 * HID];            // double-buffered fp16 h
__device__ __align__(16) float  g_feat[4 * HID];
__device__ __align__(16) float  g_hid[HID];
__device__ int g_bar;

__global__ void prep_kernel(const float* __restrict__ Whh) {
    size_t idx = (size_t)blockIdx.x * blockDim.x + threadIdx.x;
    size_t stride = (size_t)gridDim.x * blockDim.x;
    const size_t total = (size_t)FH * HID;
    for (size_t i = idx; i < total; i += stride)
        g_Whh[i] = __float2half(Whh[i]);
    if (idx == 0) g_bar = 0;   // reset every launch (graph replay!)
}

// no-op kernels: shift lstm_kernel into ncu's profiled launch slot (-s 5 -c 1)
__global__ void dummy_kernel() {}

__device__ __forceinline__ float sigf(float v) {
    return __fdividef(1.f, 1.f + __expf(-v));
}
__device__ __forceinline__ float tanhx(float v) {
    // tanh(v) = 2*sigmoid(2v) - 1 ; __expf err ~2ulp, safe over 8192 steps
    return fmaf(2.f, sigf(2.f * v), -1.f);
}

__global__ void __launch_bounds__(TPB, 1) lstm_kernel(
    const float* __restrict__ x,
    const float* __restrict__ last_dist,
    const float* __restrict__ last_heading,
    const float* __restrict__ Wih,
    const float* __restrict__ bih,
    const float* __restrict__ bhh)
{
    extern __shared__ char sm_raw[];
    __half* ws    = (__half*)sm_raw;                       // [32][2048] gate rows s=2,3
    __half* hs    = (__half*)(sm_raw + SMEM_W_BYTES);      // [2048] h stage (fp16)
    float*  bsm   = (float*)(sm_raw + SMEM_W_BYTES + HID * 2);  // [64]
    float*  wihsm = bsm + 64;                              // [64][3]

    const int tid = threadIdx.x;
    const int w   = tid >> 5;
    const int l   = tid & 31;
    const int blk = blockIdx.x;

    // ---- stage weights: warp w owns gate rows s=0..3 (global row s*HID + blk*16 + w).
    // s=0,1 in registers (uint4 = 8 halves, lane l covers cols 8l+256i), s=2,3 in smem.
    uint4 wreg0[8], wreg1[8];
    {
        const uint4* gp = (const uint4*)(g_Whh + ((size_t)blk * JPC + w) * HID);
        #pragma unroll
        for (int i = 0; i < 8; i++) wreg0[i] = gp[l + 32 * i];
        gp = (const uint4*)(g_Whh + ((size_t)HID + blk * JPC + w) * HID);
        #pragma unroll
        for (int i = 0; i < 8; i++) wreg1[i] = gp[l + 32 * i];
    }
    #pragma unroll
    for (int s = 2; s < 4; s++) {
        const uint4* gp = (const uint4*)(g_Whh + ((size_t)s * HID + blk * JPC + w) * HID);
        uint4* sp = (uint4*)(ws + (size_t)(2 * w + (s - 2)) * HID);
        #pragma unroll
        for (int i = 0; i < 8; i++) sp[l + 32 * i] = gp[l + 32 * i];
    }
    // biases + W_ih rows for this CTA's 64 gate rows -> smem (read by lane0 only)
    if (tid < 64) {
        int s = tid >> 4, j = tid & 15;
        size_t grow = (size_t)s * HID + (size_t)blk * JPC + j;
        bsm[(j << 2) | s] = bih[grow] + bhh[grow];     // bsm[j*4+s]
        wihsm[((j << 2) | s) * 3 + 0] = Wih[grow * 3 + 0];
        wihsm[((j << 2) | s) * 3 + 1] = Wih[grow * 3 + 1];
        wihsm[((j << 2) | s) * 3 + 2] = Wih[grow * 3 + 2];
    }
    // h0 = 0 in the fp16 stage
    if (tid < 256) ((uint4*)hs)[tid] = make_uint4(0, 0, 0, 0);
    float creg = 0.f;
    __syncthreads();

    const __half2 h2z = __float2half2_rn(0.f);

    for (int t = 0; t <= TLEN; t++) {
        // lane0: prefetch x_t (hidden behind the dot products)
        float x0 = 0.f, x1 = 0.f, x2 = 0.f;
        if (l == 0 && t < TLEN) {
            x0 = __ldg(x + 3 * t);
            x1 = __ldg(x + 3 * t + 1);
            x2 = __ldg(x + 3 * t + 2);
        }

        // ---- snapshot h (fp16) into registers: lane l covers cols 8l+256i
        uint4 hreg[8];
        {
            const uint4* hp = (const uint4*)hs;
            #pragma unroll
            for (int i = 0; i < 8; i++) hreg[i] = hp[l + 32 * i];
        }
        __syncthreads();   // hs free for next-step staging

        // ---- 4 gate dot products, HFMA2 chains of 16 products -> fp32 flush
        float acc[4];
        #pragma unroll
        for (int s = 0; s < 4; s++) {
            const uint4* wp = (const uint4*)(ws + (size_t)(2 * w + (s - 2)) * HID);
            __half2 c0 = h2z, c1 = h2z;
            float a0 = 0.f, a1 = 0.f;
            #pragma unroll
            for (int i = 0; i < 8; i++) {
                uint4 u = (s == 0) ? wreg0[i] : (s == 1) ? wreg1[i] : wp[l + 32 * i];
                uint4 hv = hreg[i];
                c0 = __hfma2(*(__half2*)&u.x, *(__half2*)&hv.x, c0);
                c1 = __hfma2(*(__half2*)&u.y, *(__half2*)&hv.y, c1);
                c0 = __hfma2(*(__half2*)&u.z, *(__half2*)&hv.z, c0);
                c1 = __hfma2(*(__half2*)&u.w, *(__half2*)&hv.w, c1);
                if (i == 3 || i == 7) {
                    float2 f0 = __half22float2(c0);
                    float2 f1 = __half22float2(c1);
                    a0 += f0.x + f1.x;
                    a1 += f0.y + f1.y;
                    c0 = h2z; c1 = h2z;
                }
            }
            float a = a0 + a1;
            #pragma unroll
            for (int off = 16; off > 0; off >>= 1)
                a += __shfl_xor_sync(0xffffffffu, a, off);
            acc[s] = a;
        }

        // ---- cell update in lane 0 of warp w (= h-lane blk*16+w)
        if (l == 0) {
            const float* bp = bsm + (w << 2);
            const float* wp = wihsm + (w << 2) * 3;
            if (t < TLEN) {
                float gi = acc[0] + bp[0] + wp[0] * x0 + wp[1]  * x1 + wp[2]  * x2;
                float gf = acc[1] + bp[1] + wp[3] * x0 + wp[4]  * x1 + wp[5]  * x2;
                float gg = acc[2] + bp[2] + wp[6] * x0 + wp[7]  * x1 + wp[8]  * x2;
                float go = acc[3] + bp[3] + wp[9] * x0 + wp[10] * x1 + wp[11] * x2;
                float c = sigf(gf) * creg + sigf(gi) * tanhx(gg);
                creg = c;
                unsigned short hb = __half_as_ushort(__float2half(sigf(go) * tanhx(c)));
                asm volatile("st.global.cg.u16 [%0], %1;"
                             :: "l"(g_hh + ((t + 1) & 1) * HID + blk * JPC + w), "h"(hb));
            } else {
                // final: 4 action rollouts share W_hh@hn, differ in 3-dim x-term
                float ld = __ldg(last_dist);
                float lh = __ldg(last_heading);
                #pragma unroll
                for (int a = 0; a < 4; a++) {
                    float af = (float)a;
                    float gi = acc[0] + bp[0] + wp[0] * ld + wp[1]  * lh + wp[2]  * af;
                    float gf = acc[1] + bp[1] + wp[3] * ld + wp[4]  * lh + wp[5]  * af;
                    float gg = acc[2] + bp[2] + wp[6] * ld + wp[7]  * lh + wp[8]  * af;
                    float go = acc[3] + bp[3] + wp[9] * ld + wp[10] * lh + wp[11] * af;
                    float c = sigf(gf) * creg + sigf(gi) * tanhx(gg);
                    g_feat[a * HID + blk * JPC + w] = sigf(go) * tanhx(c);
                }
            }
        }
        if (t == TLEN) break;

        // ---- chip-wide barrier (R4-proven: threadfence + atomic counter + spin)
        __threadfence();
        __syncthreads();
        if (tid == 0) {
            atomicAdd(&g_bar, 1);
            int tgt = NCTA * (t + 1);
            while (*(volatile int*)&g_bar < tgt) { }
        }
        __syncthreads();

        // ---- stage h_{t+1} (fp16, 4KB) from global into smem
        if (tid < 256) {
            const uint4* src = (const uint4*)(g_hh + ((t + 1) & 1) * HID);
            ((uint4*)hs)[tid] = __ldcg(src + tid);
        }
        __syncthreads();
    }
}

// hid = relu(W1 @ feat + b1): 2048 rows x 8192, one warp per row (HBM-bound)
__global__ void mlp1_kernel(const float* __restrict__ W1, const float* __restrict__ b1) {
    int w = threadIdx.x >> 5, l = threadIdx.x & 31;
    int row = blockIdx.x * 8 + w;
    const float4* wp = (const float4*)(W1 + (size_t)row * FH);
    const float4* fp = (const float4*)g_feat;
    float a0 = 0.f, a1 = 0.f, a2 = 0.f, a3 = 0.f;
    #pragma unroll 8
    for (int i = 0; i < 64; i++) {
        float4 wv = wp[l + 32 * i];
        float4 fv = fp[l + 32 * i];
        a0 = fmaf(wv.x, fv.x, a0);
        a1 = fmaf(wv.y, fv.y, a1);
        a2 = fmaf(wv.z, fv.z, a2);
        a3 = fmaf(wv.w, fv.w, a3);
    }
    float a = (a0 + a1) + (a2 + a3);
    #pragma unroll
    for (int off = 16; off > 0; off >>= 1) a += __shfl_xor_sync(0xffffffffu, a, off);
    if (l == 0) g_hid[row] = fmaxf(a + b1[row], 0.f);
}

// out = W2 @ hid + b2: 4 rows x 2048, one warp each.
__global__ void mlp2_kernel(const float* __restrict__ W2, const float* __restrict__ b2,
                            float* __restrict__ out) {
    int w = threadIdx.x >> 5, l = threadIdx.x & 31;
    const float4* wp = (const float4*)(W2 + (size_t)w * HID);
    const float4* hp = (const float4*)g_hid;
    float a0 = 0.f, a1 = 0.f, a2 = 0.f, a3 = 0.f;
    #pragma unroll
    for (int i = 0; i < 16; i++) {
        float4 wv = wp[l + 32 * i];
        float4 hv = hp[l + 32 * i];
        a0 = fmaf(wv.x, hv.x, a0);
        a1 = fmaf(wv.y, hv.y, a1);
        a2 = fmaf(wv.z, hv.z, a2);
        a3 = fmaf(wv.w, hv.w, a3);
    }
    float a = (a0 + a1) + (a2 + a3);
    #pragma unroll
    for (int off = 16; off > 0; off >>= 1) a += __shfl_xor_sync(0xffffffffu, a, off);
    if (l == 0) out[w] = a + b2[w];
}

extern "C" void kernel_launch(void* const* d_in, const int* in_sizes, int n_in,
                              void* d_out, int out_size) {
    const float* x   = (const float*)d_in[0];
    const float* ld  = (const float*)d_in[1];
    const float* lh  = (const float*)d_in[2];
    const float* Wih = (const float*)d_in[3];
    const float* Whh = (const float*)d_in[4];
    const float* bih = (const float*)d_in[5];
    const float* bhh = (const float*)d_in[6];
    const float* W1  = (const float*)d_in[7];
    const float* b1  = (const float*)d_in[8];
    const float* W2  = (const float*)d_in[9];
    const float* b2  = (const float*)d_in[10];
    float* out = (float*)d_out;

    cudaFuncSetAttribute(lstm_kernel, cudaFuncAttributeMaxDynamicSharedMemorySize, SMEM_BYTES);

    prep_kernel<<<2048, 256>>>(Whh);
    dummy_kernel<<<1, 32>>>();   // shift lstm_kernel into the ncu capture slot
    dummy_kernel<<<1, 32>>>();
    lstm_kernel<<<NCTA, TPB, SMEM_BYTES>>>(x, ld, lh, Wih, bih, bhh);
    mlp1_kernel<<<HID / 8, 256>>>(W1, b1);
    mlp2_kernel<<<1, 128>>>(W2, b2, out);
}

// round 11
// speedup vs baseline: 1.6324x; 1.6324x over previous
#include <cuda_runtime.h>
#include <cuda_fp16.h>

#define HID   2048
#define FH    8192   // 4*H
#define TLEN  8192
#define NCTA  128
#define TPB   512
#define JPC   16     // h-lanes per CTA (2048/128)

// SMEM: 32 weight rows (2 per warp) * 2048 halves = 131072 B
//       + h stage 2048 halves = 4096 B + bias 64 f + wih 192 f = 1024 B
#define SMEM_W_BYTES (32 * HID * 2)
#define SMEM_BYTES   (SMEM_W_BYTES + HID * 2 + (64 + 192) * 4)

// ---- device scratch (static only; no cudaMalloc allowed) ----
__device__ __align__(16) __half g_Whh[(size_t)FH * HID];  // 32 MB fp16 weights
__device__ __align__(16) __half g_hh[2 * HID];            // double-buffered fp16 h
__device__ __align__(16) float  g_feat[4 * HID];
__device__ __align__(16) float  g_hid[HID];
__device__ unsigned g_bar;

__global__ void prep_kernel(const float* __restrict__ Whh) {
    size_t idx = (size_t)blockIdx.x * blockDim.x + threadIdx.x;
    size_t stride = (size_t)gridDim.x * blockDim.x;
    const size_t total = (size_t)FH * HID;
    for (size_t i = idx; i < total; i += stride)
        g_Whh[i] = __float2half(Whh[i]);
    if (idx == 0) g_bar = 0u;   // reset every launch (graph replay!)
}

// no-op kernels: keep lstm_kernel in ncu's profiled launch slot
__global__ void dummy_kernel() {}

__device__ __forceinline__ float sigf(float v) {
    return __fdividef(1.f, 1.f + __expf(-v));
}
__device__ __forceinline__ float tanhx(float v) {
    // tanh(v) = 2*sigmoid(2v) - 1 ; __expf err ~2ulp, safe over 8192 steps
    return fmaf(2.f, sigf(2.f * v), -1.f);
}

__global__ void __launch_bounds__(TPB, 1) lstm_kernel(
    const float* __restrict__ x,
    const float* __restrict__ last_dist,
    const float* __restrict__ last_heading,
    const float* __restrict__ Wih,
    const float* __restrict__ bih,
    const float* __restrict__ bhh)
{
    extern __shared__ char sm_raw[];
    __half* ws    = (__half*)sm_raw;                       // [32][2048] gate rows s=2,3
    __half* hs    = (__half*)(sm_raw + SMEM_W_BYTES);      // [2048] h stage (fp16)
    float*  bsm   = (float*)(sm_raw + SMEM_W_BYTES + HID * 2);  // [64]
    float*  wihsm = bsm + 64;                              // [64][3]

    const int tid = threadIdx.x;
    const int w   = tid >> 5;
    const int l   = tid & 31;
    const int blk = blockIdx.x;

    // ---- stage weights: warp w owns gate rows s=0..3 (global row s*HID + blk*16 + w).
    // s=0,1 in registers (uint4 = 8 halves, lane l covers cols 8l+256i), s=2,3 in smem.
    uint4 wreg0[8], wreg1[8];
    {
        const uint4* gp = (const uint4*)(g_Whh + ((size_t)blk * JPC + w) * HID);
        #pragma unroll
        for (int i = 0; i < 8; i++) wreg0[i] = gp[l + 32 * i];
        gp = (const uint4*)(g_Whh + ((size_t)HID + blk * JPC + w) * HID);
        #pragma unroll
        for (int i = 0; i < 8; i++) wreg1[i] = gp[l + 32 * i];
    }
    #pragma unroll
    for (int s = 2; s < 4; s++) {
        const uint4* gp = (const uint4*)(g_Whh + ((size_t)s * HID + blk * JPC + w) * HID);
        uint4* sp = (uint4*)(ws + (size_t)(2 * w + (s - 2)) * HID);
        #pragma unroll
        for (int i = 0; i < 8; i++) sp[l + 32 * i] = gp[l + 32 * i];
    }
    // biases + W_ih rows for this CTA's 64 gate rows -> smem (read by lane0 only)
    if (tid < 64) {
        int s = tid >> 4, j = tid & 15;
        size_t grow = (size_t)s * HID + (size_t)blk * JPC + j;
        bsm[(j << 2) | s] = bih[grow] + bhh[grow];     // bsm[j*4+s]
        wihsm[((j << 2) | s) * 3 + 0] = Wih[grow * 3 + 0];
        wihsm[((j << 2) | s) * 3 + 1] = Wih[grow * 3 + 1];
        wihsm[((j << 2) | s) * 3 + 2] = Wih[grow * 3 + 2];
    }
    // h0 = 0 in the fp16 stage
    if (tid < 256) ((uint4*)hs)[tid] = make_uint4(0, 0, 0, 0);
    float creg = 0.f;
    __syncthreads();

    const __half2 h2z = __float2half2_rn(0.f);

    for (int t = 0; t <= TLEN; t++) {
        // lane0: prefetch x_t (hidden behind the dot products)
        float x0 = 0.f, x1 = 0.f, x2 = 0.f;
        if (l == 0 && t < TLEN) {
            x0 = __ldg(x + 3 * t);
            x1 = __ldg(x + 3 * t + 1);
            x2 = __ldg(x + 3 * t + 2);
        }

        // ---- snapshot h (fp16) into registers: lane l covers cols 8l+256i
        uint4 hreg[8];
        {
            const uint4* hp = (const uint4*)hs;
            #pragma unroll
            for (int i = 0; i < 8; i++) hreg[i] = hp[l + 32 * i];
        }
        __syncthreads();   // hs free for next-step staging

        // ---- 4 gate dot products, HFMA2 chains of 16 products -> fp32 flush
        float acc[4];
        #pragma unroll
        for (int s = 0; s < 4; s++) {
            const uint4* wp = (const uint4*)(ws + (size_t)(2 * w + (s - 2)) * HID);
            __half2 c0 = h2z, c1 = h2z;
            float a0 = 0.f, a1 = 0.f;
            #pragma unroll
            for (int i = 0; i < 8; i++) {
                uint4 u = (s == 0) ? wreg0[i] : (s == 1) ? wreg1[i] : wp[l + 32 * i];
                uint4 hv = hreg[i];
                c0 = __hfma2(*(__half2*)&u.x, *(__half2*)&hv.x, c0);
                c1 = __hfma2(*(__half2*)&u.y, *(__half2*)&hv.y, c1);
                c0 = __hfma2(*(__half2*)&u.z, *(__half2*)&hv.z, c0);
                c1 = __hfma2(*(__half2*)&u.w, *(__half2*)&hv.w, c1);
                if (i == 3 || i == 7) {
                    float2 f0 = __half22float2(c0);
                    float2 f1 = __half22float2(c1);
                    a0 += f0.x + f1.x;
                    a1 += f0.y + f1.y;
                    c0 = h2z; c1 = h2z;
                }
            }
            float a = a0 + a1;
            #pragma unroll
            for (int off = 16; off > 0; off >>= 1)
                a += __shfl_xor_sync(0xffffffffu, a, off);
            acc[s] = a;
        }

        // ---- cell update in lane 0 of warp w (= h-lane blk*16+w)  [R4-identical]
        if (l == 0) {
            const float* bp = bsm + (w << 2);
            const float* wp = wihsm + (w << 2) * 3;
            if (t < TLEN) {
                float gi = acc[0] + bp[0] + wp[0] * x0 + wp[1]  * x1 + wp[2]  * x2;
                float gf = acc[1] + bp[1] + wp[3] * x0 + wp[4]  * x1 + wp[5]  * x2;
                float gg = acc[2] + bp[2] + wp[6] * x0 + wp[7]  * x1 + wp[8]  * x2;
                float go = acc[3] + bp[3] + wp[9] * x0 + wp[10] * x1 + wp[11] * x2;
                float c = sigf(gf) * creg + sigf(gi) * tanhx(gg);
                creg = c;
                unsigned short hb = __half_as_ushort(__float2half(sigf(go) * tanhx(c)));
                asm volatile("st.global.cg.u16 [%0], %1;"
                             :: "l"(g_hh + ((t + 1) & 1) * HID + blk * JPC + w), "h"(hb));
            } else {
                // final: 4 action rollouts share W_hh@hn, differ in 3-dim x-term
                float ld = __ldg(last_dist);
                float lh = __ldg(last_heading);
                #pragma unroll
                for (int a = 0; a < 4; a++) {
                    float af = (float)a;
                    float gi = acc[0] + bp[0] + wp[0] * ld + wp[1]  * lh + wp[2]  * af;
                    float gf = acc[1] + bp[1] + wp[3] * ld + wp[4]  * lh + wp[5]  * af;
                    float gg = acc[2] + bp[2] + wp[6] * ld + wp[7]  * lh + wp[8]  * af;
                    float go = acc[3] + bp[3] + wp[9] * ld + wp[10] * lh + wp[11] * af;
                    float c = sigf(gf) * creg + sigf(gi) * tanhx(gg);
                    g_feat[a * HID + blk * JPC + w] = sigf(go) * tanhx(c);
                }
            }
        }
        if (t == TLEN) break;

        // ---- chip-wide barrier, hybrid of the two correctness-proven variants:
        //   arrival: red.release.gpu (R6-proven correct) — replaces all-thread
        //            __threadfence + atomicAdd; release orders this CTA's prior
        //            h-store at GPU scope, no return-trip latency.
        //   wait:    cheap volatile spin (R4-proven) — no per-poll acquire cost.
        //   close:   ONE ld.acquire.gpu after detection, extended CTA-wide by
        //            the trailing __syncthreads.
        __syncthreads();
        if (tid == 0) {
            asm volatile("red.release.gpu.add.u32 [%0], 1;" :: "l"(&g_bar) : "memory");
            unsigned tgt = (unsigned)NCTA * (unsigned)(t + 1);
            while (*(volatile unsigned*)&g_bar < tgt) { }
            unsigned v;
            asm volatile("ld.acquire.gpu.u32 %0, [%1];" : "=r"(v) : "l"(&g_bar) : "memory");
        }
        __syncthreads();

        // ---- stage h_{t+1} (fp16, 4KB) from global into smem
        if (tid < 256) {
            const uint4* src = (const uint4*)(g_hh + ((t + 1) & 1) * HID);
            ((uint4*)hs)[tid] = __ldcg(src + tid);
        }
        __syncthreads();
    }
}

// hid = relu(W1 @ feat + b1): 2048 rows x 8192, one warp per row (HBM-bound)
__global__ void mlp1_kernel(const float* __restrict__ W1, const float* __restrict__ b1) {
    int w = threadIdx.x >> 5, l = threadIdx.x & 31;
    int row = blockIdx.x * 8 + w;
    const float4* wp = (const float4*)(W1 + (size_t)row * FH);
    const float4* fp = (const float4*)g_feat;
    float a0 = 0.f, a1 = 0.f, a2 = 0.f, a3 = 0.f;
    #pragma unroll 8
    for (int i = 0; i < 64; i++) {
        float4 wv = wp[l + 32 * i];
        float4 fv = fp[l + 32 * i];
        a0 = fmaf(wv.x, fv.x, a0);
        a1 = fmaf(wv.y, fv.y, a1);
        a2 = fmaf(wv.z, fv.z, a2);
        a3 = fmaf(wv.w, fv.w, a3);
    }
    float a = (a0 + a1) + (a2 + a3);
    #pragma unroll
    for (int off = 16; off > 0; off >>= 1) a += __shfl_xor_sync(0xffffffffu, a, off);
    if (l == 0) g_hid[row] = fmaxf(a + b1[row], 0.f);
}

// out = W2 @ hid + b2: 4 rows x 2048, one warp each.
__global__ void mlp2_kernel(const float* __restrict__ W2, const float* __restrict__ b2,
                            float* __restrict__ out) {
    int w = threadIdx.x >> 5, l = threadIdx.x & 31;
    const float4* wp = (const float4*)(W2 + (size_t)w * HID);
    const float4* hp = (const float4*)g_hid;
    float a0 = 0.f, a1 = 0.f, a2 = 0.f, a3 = 0.f;
    #pragma unroll
    for (int i = 0; i < 16; i++) {
        float4 wv = wp[l + 32 * i];
        float4 hv = hp[l + 32 * i];
        a0 = fmaf(wv.x, hv.x, a0);
        a1 = fmaf(wv.y, hv.y, a1);
        a2 = fmaf(wv.z, hv.z, a2);
        a3 = fmaf(wv.w, hv.w, a3);
    }
    float a = (a0 + a1) + (a2 + a3);
    #pragma unroll
    for (int off = 16; off > 0; off >>= 1) a += __shfl_xor_sync(0xffffffffu, a, off);
    if (l == 0) out[w] = a + b2[w];
}

extern "C" void kernel_launch(void* const* d_in, const int* in_sizes, int n_in,
                              void* d_out, int out_size) {
    const float* x   = (const float*)d_in[0];
    const float* ld  = (const float*)d_in[1];
    const float* lh  = (const float*)d_in[2];
    const float* Wih = (const float*)d_in[3];
    const float* Whh = (const float*)d_in[4];
    const float* bih = (const float*)d_in[5];
    const float* bhh = (const float*)d_in[6];
    const float* W1  = (const float*)d_in[7];
    const float* b1  = (const float*)d_in[8];
    const float* W2  = (const float*)d_in[9];
    const float* b2  = (const float*)d_in[10];
    float* out = (float*)d_out;

    cudaFuncSetAttribute(lstm_kernel, cudaFuncAttributeMaxDynamicSharedMemorySize, SMEM_BYTES);

    prep_kernel<<<2048, 256>>>(Whh);
    dummy_kernel<<<1, 32>>>();   // keep lstm_kernel in the ncu capture slot
    dummy_kernel<<<1, 32>>>();
    lstm_kernel<<<NCTA, TPB, SMEM_BYTES>>>(x, ld, lh, Wih, bih, bhh);
    mlp1_kernel<<<HID / 8, 256>>>(W1, b1);
    mlp2_kernel<<<1, 128>>>(W2, b2, out);
}